// round 1
// baseline (speedup 1.0000x reference)
#include <cuda_runtime.h>

#define CH   256      // Cin = Cout
#define FF   512
#define NB   2048     // T*H*W
#define BATCH 8
#define NELEM (BATCH*CH*NB)   // 4,194,304
#define BN_COUNT 16384.0f     // B*T*H*W per channel

// Scratch (no allocations allowed)
__device__ float g_Weff[CH*CH];
__device__ float g_sum[CH];
__device__ float g_sumsq[CH];
__device__ float g_scale[CH];
__device__ float g_bias[CH];

// ---------------------------------------------------------------------------
// Kernel A: W_eff[o][c] = sum_f Wout[o][f] * Wv[f][c]   (256x512 @ 512x256)
// grid (8,8), 256 threads, 32x32 tile per block. Also zeroes BN accumulators.
// ---------------------------------------------------------------------------
__global__ void weff_kernel(const float* __restrict__ Wout,
                            const float* __restrict__ Wv) {
    __shared__ float As[32][33];  // Wout tile [oc][f]
    __shared__ float Bs[32][33];  // Wv   tile [f][c]
    int tid = threadIdx.x;
    if (blockIdx.x == 0 && blockIdx.y == 0) {
        g_sum[tid] = 0.f;
        g_sumsq[tid] = 0.f;
    }
    int oc0 = blockIdx.y * 32, c0 = blockIdx.x * 32;
    int tr = tid >> 5;          // 0..7
    int tc = tid & 31;          // 0..31
    float acc[4] = {0.f, 0.f, 0.f, 0.f};
    for (int f0 = 0; f0 < FF; f0 += 32) {
        #pragma unroll
        for (int i = 0; i < 4; i++) {
            int idx = tid * 4 + i;
            int r = idx >> 5, k = idx & 31;
            As[r][k] = Wout[(oc0 + r) * FF + f0 + k];
            Bs[r][k] = Wv[(f0 + r) * CH + c0 + k];
        }
        __syncthreads();
        #pragma unroll
        for (int k = 0; k < 32; k++) {
            float b = Bs[k][tc];
            #pragma unroll
            for (int q = 0; q < 4; q++)
                acc[q] += As[tr + 8 * q][k] * b;
        }
        __syncthreads();
    }
    #pragma unroll
    for (int q = 0; q < 4; q++)
        g_Weff[(oc0 + tr + 8 * q) * CH + c0 + tc] = acc[q];
}

// ---------------------------------------------------------------------------
// Kernel B: per batch, o = W_eff @ x[b];  y = x + relu(o + bout)
// Writes y to out, accumulates per-channel sum / sumsq.
// grid (NB/64, BATCH) = (32, 8), 256 threads.
// Tile: M=256 (all channels) x Nt=64 cols. Thread: 8 rows x 8 cols.
// ---------------------------------------------------------------------------
__global__ void __launch_bounds__(256, 2)
gemm_kernel(const float* __restrict__ x,
            const float* __restrict__ bout,
            float* __restrict__ out) {
    __shared__ float xs[16][64];        // x chunk  [kk][n]
    __shared__ float ws[16][260];       // W_eff chunk transposed [kk][row] (pad for banks+align)
    __shared__ float s_red[2 * CH];     // per-block channel partials (sum, sumsq)

    int b  = blockIdx.y;
    int n0 = blockIdx.x * 64;
    const float* xb = x   + (size_t)b * CH * NB;
    float*       ob = out + (size_t)b * CH * NB;

    int tid  = threadIdx.x;
    int row0 = (tid >> 3) * 8;   // 0,8,...,248
    int col0 = (tid & 7) * 8;    // 0,8,...,56

    s_red[tid] = 0.f;
    s_red[tid + CH] = 0.f;

    float acc[8][8];
    #pragma unroll
    for (int i = 0; i < 8; i++)
        #pragma unroll
        for (int j = 0; j < 8; j++) acc[i][j] = 0.f;

    for (int k0 = 0; k0 < CH; k0 += 16) {
        // stage x chunk: 16x64 floats, 4 per thread (coalesced float4)
        {
            int k = tid >> 4;
            int n = (tid & 15) * 4;
            float4 v = *(const float4*)&xb[(size_t)(k0 + k) * NB + n0 + n];
            *(float4*)&xs[k][n] = v;
        }
        // stage W_eff chunk transposed: 16x256 floats, 16 per thread
        #pragma unroll
        for (int i = 0; i < 16; i++) {
            int e  = tid + i * 256;
            int r  = e >> 4;
            int kk = e & 15;
            ws[kk][r] = g_Weff[r * CH + k0 + kk];
        }
        __syncthreads();

        #pragma unroll
        for (int kk = 0; kk < 16; kk++) {
            float4 a0 = *(float4*)&ws[kk][row0];
            float4 a1 = *(float4*)&ws[kk][row0 + 4];
            float4 b0 = *(float4*)&xs[kk][col0];
            float4 b1 = *(float4*)&xs[kk][col0 + 4];
            float a[8] = {a0.x, a0.y, a0.z, a0.w, a1.x, a1.y, a1.z, a1.w};
            float bb[8] = {b0.x, b0.y, b0.z, b0.w, b1.x, b1.y, b1.z, b1.w};
            #pragma unroll
            for (int i = 0; i < 8; i++)
                #pragma unroll
                for (int j = 0; j < 8; j++)
                    acc[i][j] += a[i] * bb[j];
        }
        __syncthreads();
    }

    // Epilogue: bias, relu, residual, store, BN partial sums
    #pragma unroll
    for (int i = 0; i < 8; i++) {
        int r = row0 + i;
        float bo = bout[r];
        float4 xa = *(const float4*)&xb[(size_t)r * NB + n0 + col0];
        float4 xc = *(const float4*)&xb[(size_t)r * NB + n0 + col0 + 4];
        float xv[8] = {xa.x, xa.y, xa.z, xa.w, xc.x, xc.y, xc.z, xc.w};
        float yv[8];
        float ps = 0.f, pq = 0.f;
        #pragma unroll
        for (int j = 0; j < 8; j++) {
            float o = fmaxf(acc[i][j] + bo, 0.f);
            float y = xv[j] + o;
            yv[j] = y;
            ps += y;
            pq += y * y;
        }
        float4 o0 = make_float4(yv[0], yv[1], yv[2], yv[3]);
        float4 o1 = make_float4(yv[4], yv[5], yv[6], yv[7]);
        *(float4*)&ob[(size_t)r * NB + n0 + col0]     = o0;
        *(float4*)&ob[(size_t)r * NB + n0 + col0 + 4] = o1;
        atomicAdd(&s_red[r], ps);
        atomicAdd(&s_red[CH + r], pq);
    }
    __syncthreads();
    atomicAdd(&g_sum[tid],   s_red[tid]);
    atomicAdd(&g_sumsq[tid], s_red[tid + CH]);
}

// ---------------------------------------------------------------------------
// Kernel C: fold BN stats into per-channel scale/bias.  <<<1,256>>>
// ---------------------------------------------------------------------------
__global__ void stats_kernel(const float* __restrict__ gamma,
                             const float* __restrict__ beta) {
    int c = threadIdx.x;
    float m = g_sum[c] / BN_COUNT;
    float v = g_sumsq[c] / BN_COUNT - m * m;
    float s = gamma[c] * rsqrtf(v + 1e-5f);
    g_scale[c] = s;
    g_bias[c]  = beta[c] - m * s;
}

// ---------------------------------------------------------------------------
// Kernel D: in-place normalize out.  float4, grid 4096 x 256.
// ---------------------------------------------------------------------------
__global__ void norm_kernel(float* __restrict__ out) {
    int i = blockIdx.x * blockDim.x + threadIdx.x;   // float4 index
    int c = (i >> 9) & 255;                          // (i*4 / 2048) % 256
    float s = g_scale[c];
    float b = g_bias[c];
    float4 v = ((float4*)out)[i];
    v.x = v.x * s + b;
    v.y = v.y * s + b;
    v.z = v.z * s + b;
    v.w = v.w * s + b;
    ((float4*)out)[i] = v;
}

// ---------------------------------------------------------------------------
extern "C" void kernel_launch(void* const* d_in, const int* in_sizes, int n_in,
                              void* d_out, int out_size) {
    const float* x     = (const float*)d_in[0];
    // d_in[1] = Wk, d_in[2] = Wq  -> provably unused (softmax row-sums == 1)
    const float* Wv    = (const float*)d_in[3];
    const float* Wout  = (const float*)d_in[4];
    const float* bout  = (const float*)d_in[5];
    const float* gamma = (const float*)d_in[6];
    const float* beta  = (const float*)d_in[7];
    float* out = (float*)d_out;

    weff_kernel<<<dim3(8, 8), 256>>>(Wout, Wv);
    gemm_kernel<<<dim3(NB / 64, BATCH), 256>>>(x, bout, out);
    stats_kernel<<<1, 256>>>(gamma, beta);
    norm_kernel<<<NELEM / 4 / 256, 256>>>(out);
}

// round 3
// speedup vs baseline: 1.6974x; 1.6974x over previous
#include <cuda_runtime.h>
#include <cstdint>

#define CH    256
#define FF    512
#define NB    2048
#define BATCH 8
#define NELEM (BATCH*CH*NB)
#define BN_COUNT 16384.0f

#define MT 128          // CTA M tile
#define NT 128          // CTA N tile
#define KC 32           // K chunk
#define A_STRIDE 36     // padded floats per A row
#define B_STRIDE 132    // padded floats per B row

// dynamic smem float offsets
#define A_BUF_FL   (MT * A_STRIDE)          // 4608
#define B_BUF_FL   (KC * B_STRIDE)          // 4224
#define OFF_A      0
#define OFF_B      (2 * A_BUF_FL)           // 9216
#define OFF_RED    (OFF_B + 2 * B_BUF_FL)   // 17664
#define SMEM_FL    (OFF_RED + 256)          // 17920 floats
#define SMEM_BYTES (SMEM_FL * 4)            // 71680

// Scratch globals (no allocations allowed)
__device__ float g_Weff[CH*CH];
__device__ float g_sum[CH];
__device__ float g_sumsq[CH];

__device__ __forceinline__ uint32_t smem_u32(const void* p) {
    uint32_t a;
    asm("{ .reg .u64 t; cvta.to.shared.u64 t, %1; cvt.u32.u64 %0, t; }" : "=r"(a) : "l"(p));
    return a;
}
__device__ __forceinline__ void cp_async16(uint32_t dst, const void* src) {
    asm volatile("cp.async.cg.shared.global [%0], [%1], 16;" :: "r"(dst), "l"(src));
}
__device__ __forceinline__ void cp_commit() {
    asm volatile("cp.async.commit_group;");
}
__device__ __forceinline__ uint32_t f2tf32(float f) {
    uint32_t u;
    asm("cvt.rna.tf32.f32 %0, %1;" : "=r"(u) : "f"(f));
    return u;
}
__device__ __forceinline__ void mma_tf32(float* d, const uint32_t* a, const uint32_t* b) {
    asm volatile(
        "mma.sync.aligned.m16n8k8.row.col.f32.tf32.tf32.f32 "
        "{%0,%1,%2,%3}, {%4,%5,%6,%7}, {%8,%9}, {%0,%1,%2,%3};"
        : "+f"(d[0]), "+f"(d[1]), "+f"(d[2]), "+f"(d[3])
        : "r"(a[0]), "r"(a[1]), "r"(a[2]), "r"(a[3]), "r"(b[0]), "r"(b[1]));
}

// ---------------------------------------------------------------------------
// Kernel A: W_eff = Wout @ Wv  (256x512 @ 512x256), SIMT fp32. Zeroes BN sums.
// ---------------------------------------------------------------------------
__global__ void weff_kernel(const float* __restrict__ Wout,
                            const float* __restrict__ Wv) {
    __shared__ float As[32][33];
    __shared__ float Bs[32][33];
    int tid = threadIdx.x;
    if (blockIdx.x == 0 && blockIdx.y == 0) {
        g_sum[tid] = 0.f;
        g_sumsq[tid] = 0.f;
    }
    int oc0 = blockIdx.y * 32, c0 = blockIdx.x * 32;
    int tr = tid >> 5, tc = tid & 31;
    float acc[4] = {0.f, 0.f, 0.f, 0.f};
    for (int f0 = 0; f0 < FF; f0 += 32) {
        #pragma unroll
        for (int i = 0; i < 4; i++) {
            int idx = tid * 4 + i;
            int r = idx >> 5, k = idx & 31;
            As[r][k] = Wout[(oc0 + r) * FF + f0 + k];
            Bs[r][k] = Wv[(f0 + r) * CH + c0 + k];
        }
        __syncthreads();
        #pragma unroll
        for (int k = 0; k < 32; k++) {
            float b = Bs[k][tc];
            #pragma unroll
            for (int q = 0; q < 4; q++)
                acc[q] += As[tr + 8 * q][k] * b;
        }
        __syncthreads();
    }
    #pragma unroll
    for (int q = 0; q < 4; q++)
        g_Weff[(oc0 + tr + 8 * q) * CH + c0 + tc] = acc[q];
}

// ---------------------------------------------------------------------------
// Kernel B: tf32 mma.sync GEMM + fused epilogue.
// Per CTA: O[128,128] = W_eff[mBase:+128, :256] @ x_b[:, n0:n0+128]
// grid (16, 2, 8) = (n-tiles, m-tiles, batch), 256 threads (8 warps).
// Warp tile 32(m) x 64(n): 2 x 8 mma.m16n8k8.
// ---------------------------------------------------------------------------
__global__ void __launch_bounds__(256, 2)
gemm_tc_kernel(const float* __restrict__ x,
               const float* __restrict__ bout,
               float* __restrict__ out) {
    extern __shared__ float smf[];
    uint32_t smb = smem_u32(smf);

    int tid  = threadIdx.x;
    int wid  = tid >> 5;
    int lane = tid & 31;
    int r    = lane >> 2;        // groupID
    int t    = lane & 3;         // threadInGroup
    int wRow = wid & 3;          // 0..3 -> m offset *32
    int wCol = wid >> 2;         // 0..1 -> n offset *64

    int n0    = blockIdx.x * NT;
    int mBase = blockIdx.y * MT;
    int b     = blockIdx.z;
    const float* xb = x   + (size_t)b * CH * NB;
    float*       ob = out + (size_t)b * CH * NB;

    smf[OFF_RED + tid] = 0.f;    // zero 256 reduction slots (sum[128], sumsq[128])

    float acc[2][8][4];
    #pragma unroll
    for (int mt = 0; mt < 2; mt++)
        #pragma unroll
        for (int nt = 0; nt < 8; nt++)
            #pragma unroll
            for (int q = 0; q < 4; q++) acc[mt][nt][q] = 0.f;

    // ---- async load helpers (inline) ----
    // A chunk: W_eff[mBase+m][k0+k], m 0..127, k 0..31
    // B chunk: x[k0+k][n0+n],        k 0..31,  n 0..127
    #define LOAD_CHUNK(buf, k0)                                                    \
    {                                                                              \
        uint32_t adst = smb + (OFF_A + (buf) * A_BUF_FL) * 4;                      \
        uint32_t bdst = smb + (OFF_B + (buf) * B_BUF_FL) * 4;                      \
        _Pragma("unroll")                                                          \
        for (int it = 0; it < 4; it++) {                                           \
            int idx = tid + it * 256;                                              \
            int m = idx >> 3, k4 = idx & 7;                                        \
            cp_async16(adst + (m * A_STRIDE + k4 * 4) * 4,                         \
                       &g_Weff[(mBase + m) * CH + (k0) + k4 * 4]);                 \
        }                                                                          \
        _Pragma("unroll")                                                          \
        for (int it = 0; it < 4; it++) {                                           \
            int idx = tid + it * 256;                                              \
            int k = idx >> 5, n4 = idx & 31;                                       \
            cp_async16(bdst + (k * B_STRIDE + n4 * 4) * 4,                         \
                       &xb[(size_t)((k0) + k) * NB + n0 + n4 * 4]);                \
        }                                                                          \
    }

    LOAD_CHUNK(0, 0);
    cp_commit();

    for (int i = 0; i < 8; i++) {
        int buf = i & 1;
        if (i < 7) {
            LOAD_CHUNK((i + 1) & 1, (i + 1) * KC);
            cp_commit();
            asm volatile("cp.async.wait_group 1;");
        } else {
            asm volatile("cp.async.wait_group 0;");
        }
        __syncthreads();

        const float* Ab = smf + OFF_A + buf * A_BUF_FL;
        const float* Bb = smf + OFF_B + buf * B_BUF_FL;

        #pragma unroll
        for (int kc = 0; kc < 4; kc++) {
            int k8 = kc * 8;
            uint32_t afr[2][4];
            #pragma unroll
            for (int mt = 0; mt < 2; mt++) {
                int m = wRow * 32 + mt * 16 + r;
                afr[mt][0] = f2tf32(Ab[m * A_STRIDE + k8 + t]);
                afr[mt][1] = f2tf32(Ab[(m + 8) * A_STRIDE + k8 + t]);
                afr[mt][2] = f2tf32(Ab[m * A_STRIDE + k8 + t + 4]);
                afr[mt][3] = f2tf32(Ab[(m + 8) * A_STRIDE + k8 + t + 4]);
            }
            uint32_t bfr[8][2];
            #pragma unroll
            for (int nt = 0; nt < 8; nt++) {
                int n = wCol * 64 + nt * 8 + r;
                bfr[nt][0] = f2tf32(Bb[(k8 + t) * B_STRIDE + n]);
                bfr[nt][1] = f2tf32(Bb[(k8 + t + 4) * B_STRIDE + n]);
            }
            #pragma unroll
            for (int mt = 0; mt < 2; mt++)
                #pragma unroll
                for (int nt = 0; nt < 8; nt++)
                    mma_tf32(acc[mt][nt], afr[mt], bfr[nt]);
        }
        __syncthreads();
    }

    // ---------------- epilogue ----------------
    float* s_red = smf + OFF_RED;
    #pragma unroll
    for (int mt = 0; mt < 2; mt++) {
        #pragma unroll
        for (int rv = 0; rv < 2; rv++) {            // row variant: +0 / +8
            int rl = wRow * 32 + mt * 16 + rv * 8 + r;   // local row
            int rg = mBase + rl;                          // global channel
            float bo = bout[rg];
            float ps = 0.f, pq = 0.f;
            #pragma unroll
            for (int nt = 0; nt < 8; nt++) {
                int col = n0 + wCol * 64 + nt * 8 + t * 2;
                size_t gi = (size_t)rg * NB + col;
                float2 xv = *(const float2*)&xb[gi];
                float o0 = fmaxf(acc[mt][nt][rv * 2 + 0] + bo, 0.f);
                float o1 = fmaxf(acc[mt][nt][rv * 2 + 1] + bo, 0.f);
                float y0 = xv.x + o0;
                float y1 = xv.y + o1;
                *(float2*)&ob[gi] = make_float2(y0, y1);
                ps += y0 + y1;
                pq += y0 * y0 + y1 * y1;
            }
            atomicAdd(&s_red[rl], ps);
            atomicAdd(&s_red[128 + rl], pq);
        }
    }
    __syncthreads();
    if (tid < 128) {
        atomicAdd(&g_sum[mBase + tid],   s_red[tid]);
        atomicAdd(&g_sumsq[mBase + tid], s_red[128 + tid]);
    }
}

// ---------------------------------------------------------------------------
// Kernel C: fused BN stats + normalize (in place). 1024 blocks x 256 thr x 4 f4.
// ---------------------------------------------------------------------------
__global__ void norm_kernel(float* __restrict__ out,
                            const float* __restrict__ gamma,
                            const float* __restrict__ beta) {
    int base = blockIdx.x * 1024 + threadIdx.x;
    #pragma unroll
    for (int j = 0; j < 4; j++) {
        int i = base + j * 256;               // float4 index
        int c = (i >> 9) & 255;
        float m = g_sum[c] * (1.0f / BN_COUNT);
        float v = g_sumsq[c] * (1.0f / BN_COUNT) - m * m;
        float sc = gamma[c] * rsqrtf(v + 1e-5f);
        float bi = beta[c] - m * sc;
        float4 tv = ((float4*)out)[i];
        tv.x = tv.x * sc + bi;
        tv.y = tv.y * sc + bi;
        tv.z = tv.z * sc + bi;
        tv.w = tv.w * sc + bi;
        ((float4*)out)[i] = tv;
    }
}

// ---------------------------------------------------------------------------
extern "C" void kernel_launch(void* const* d_in, const int* in_sizes, int n_in,
                              void* d_out, int out_size) {
    const float* x     = (const float*)d_in[0];
    // d_in[1] = Wk, d_in[2] = Wq  -> provably unused (softmax row-sums == 1)
    const float* Wv    = (const float*)d_in[3];
    const float* Wout  = (const float*)d_in[4];
    const float* bout  = (const float*)d_in[5];
    const float* gamma = (const float*)d_in[6];
    const float* beta  = (const float*)d_in[7];
    float* out = (float*)d_out;

    cudaFuncSetAttribute(gemm_tc_kernel,
                         cudaFuncAttributeMaxDynamicSharedMemorySize, SMEM_BYTES);

    weff_kernel<<<dim3(8, 8), 256>>>(Wout, Wv);
    gemm_tc_kernel<<<dim3(NB / NT, CH / MT, BATCH), 256, SMEM_BYTES>>>(x, bout, out);
    norm_kernel<<<NELEM / 4 / 1024, 256>>>(out, gamma, beta);
}

// round 4
// speedup vs baseline: 2.0014x; 1.1791x over previous
#include <cuda_runtime.h>
#include <cstdint>

#define CH    256
#define FF    512
#define NB    2048
#define BATCH 8
#define NELEM (BATCH*CH*NB)
#define BN_COUNT 16384.0f
#define GRID_TOTAL 256u     // fused kernel CTA count (16*2*8)

#define MT 128          // CTA M tile
#define NT 128          // CTA N tile
#define KC 32           // K chunk
#define A_STRIDE 36     // padded floats per A row
#define B_STRIDE 132    // padded floats per B row

// dynamic smem float offsets
#define A_BUF_FL   (MT * A_STRIDE)          // 4608
#define B_BUF_FL   (KC * B_STRIDE)          // 4224
#define OFF_A      0
#define OFF_B      (2 * A_BUF_FL)           // 9216
#define OFF_RED    (OFF_B + 2 * B_BUF_FL)   // 17664
#define SMEM_FL    (OFF_RED + 256)          // 17920 floats
#define SMEM_BYTES (SMEM_FL * 4)            // 71680

// Scratch globals (no allocations allowed)
__device__ float    g_Weff[CH*CH];
__device__ float    g_sum[CH];
__device__ float    g_sumsq[CH];
__device__ unsigned g_bar;

__device__ __forceinline__ uint32_t smem_u32(const void* p) {
    uint32_t a;
    asm("{ .reg .u64 t; cvta.to.shared.u64 t, %1; cvt.u32.u64 %0, t; }" : "=r"(a) : "l"(p));
    return a;
}
__device__ __forceinline__ void cp_async16(uint32_t dst, const void* src) {
    asm volatile("cp.async.cg.shared.global [%0], [%1], 16;" :: "r"(dst), "l"(src));
}
__device__ __forceinline__ void cp_commit() {
    asm volatile("cp.async.commit_group;");
}
__device__ __forceinline__ uint32_t f2tf32(float f) {
    uint32_t u;
    asm("cvt.rna.tf32.f32 %0, %1;" : "=r"(u) : "f"(f));
    return u;
}
__device__ __forceinline__ void mma_tf32(float* d, const uint32_t* a, const uint32_t* b) {
    asm volatile(
        "mma.sync.aligned.m16n8k8.row.col.f32.tf32.tf32.f32 "
        "{%0,%1,%2,%3}, {%4,%5,%6,%7}, {%8,%9}, {%0,%1,%2,%3};"
        : "+f"(d[0]), "+f"(d[1]), "+f"(d[2]), "+f"(d[3])
        : "r"(a[0]), "r"(a[1]), "r"(a[2]), "r"(a[3]), "r"(b[0]), "r"(b[1]));
}

// ---------------------------------------------------------------------------
// Kernel 0: zero g_Weff + BN accumulators + barrier counter. grid 64 x 256.
// ---------------------------------------------------------------------------
__global__ void zero_kernel() {
    int i = blockIdx.x * 256 + threadIdx.x;        // 0..16383 float4 slots
    ((float4*)g_Weff)[i] = make_float4(0.f, 0.f, 0.f, 0.f);
    if (blockIdx.x == 0) {
        g_sum[threadIdx.x]   = 0.f;
        g_sumsq[threadIdx.x] = 0.f;
        if (threadIdx.x == 0) g_bar = 0u;
    }
}

// ---------------------------------------------------------------------------
// Kernel A: W_eff += Wout @ Wv  (256x512 @ 512x256), split-K SIMT.
// grid (4,4,4) = (c-tile, o-tile, k-slice). 256 threads, 4x4 regs/thread.
// ---------------------------------------------------------------------------
__global__ void __launch_bounds__(256, 4)
weff_kernel(const float* __restrict__ Wout,
            const float* __restrict__ Wv) {
    __shared__ float Ws[64][33];   // Wout tile [o][k]
    __shared__ float Vs[32][68];   // Wv   tile [k][c]

    int tid = threadIdx.x;
    int to  = tid >> 4;            // 0..15
    int tc  = tid & 15;            // 0..15
    int c0  = blockIdx.x * 64;
    int o0  = blockIdx.y * 64;
    int k0  = blockIdx.z * 128;

    float acc[4][4];
    #pragma unroll
    for (int i = 0; i < 4; i++)
        #pragma unroll
        for (int j = 0; j < 4; j++) acc[i][j] = 0.f;

    for (int kc = 0; kc < 4; kc++) {
        int kb = k0 + kc * 32;
        // Ws: 64x32, 8 elems/thread, coalesced on k
        #pragma unroll
        for (int it = 0; it < 8; it++) {
            int idx = tid + it * 256;
            int r = idx >> 5, kk = idx & 31;
            Ws[r][kk] = Wout[(o0 + r) * FF + kb + kk];
        }
        // Vs: 32x64, 8 elems/thread, coalesced on c
        #pragma unroll
        for (int it = 0; it < 8; it++) {
            int idx = tid + it * 256;
            int kk = idx >> 6, cc = idx & 63;
            Vs[kk][cc] = Wv[(size_t)(kb + kk) * CH + c0 + cc];
        }
        __syncthreads();
        #pragma unroll
        for (int kk = 0; kk < 32; kk++) {
            float4 b = *(const float4*)&Vs[kk][tc * 4];
            float bv[4] = {b.x, b.y, b.z, b.w};
            #pragma unroll
            for (int i = 0; i < 4; i++) {
                float a = Ws[to * 4 + i][kk];
                #pragma unroll
                for (int j = 0; j < 4; j++)
                    acc[i][j] += a * bv[j];
            }
        }
        __syncthreads();
    }
    #pragma unroll
    for (int i = 0; i < 4; i++)
        #pragma unroll
        for (int j = 0; j < 4; j++)
            atomicAdd(&g_Weff[(o0 + to * 4 + i) * CH + c0 + tc * 4 + j], acc[i][j]);
}

// ---------------------------------------------------------------------------
// Kernel B: tf32 mma.sync GEMM + fused stats + grid barrier + fused BN norm.
// Per CTA: O[128,128] = W_eff[mBase:+128, :256] @ x_b[:, n0:n0+128]
// grid (16, 2, 8) = 256 CTAs (all co-resident: launch_bounds(256,2)).
// ---------------------------------------------------------------------------
__global__ void __launch_bounds__(256, 2)
fused_kernel(const float* __restrict__ x,
             const float* __restrict__ bout,
             float* __restrict__ out) {
    extern __shared__ float smf[];
    uint32_t smb = smem_u32(smf);

    int tid  = threadIdx.x;
    int wid  = tid >> 5;
    int lane = tid & 31;
    int r    = lane >> 2;        // groupID
    int t    = lane & 3;         // threadInGroup
    int wRow = wid & 3;          // m offset *32
    int wCol = wid >> 2;         // n offset *64

    int n0    = blockIdx.x * NT;
    int mBase = blockIdx.y * MT;
    int b     = blockIdx.z;
    const float* xb = x   + (size_t)b * CH * NB;
    float*       ob = out + (size_t)b * CH * NB;

    smf[OFF_RED + tid] = 0.f;

    float acc[2][8][4];
    #pragma unroll
    for (int mt = 0; mt < 2; mt++)
        #pragma unroll
        for (int nt = 0; nt < 8; nt++)
            #pragma unroll
            for (int q = 0; q < 4; q++) acc[mt][nt][q] = 0.f;

    #define LOAD_CHUNK(buf, k0)                                                    \
    {                                                                              \
        uint32_t adst = smb + (OFF_A + (buf) * A_BUF_FL) * 4;                      \
        uint32_t bdst = smb + (OFF_B + (buf) * B_BUF_FL) * 4;                      \
        _Pragma("unroll")                                                          \
        for (int it = 0; it < 4; it++) {                                           \
            int idx = tid + it * 256;                                              \
            int m = idx >> 3, k4 = idx & 7;                                        \
            cp_async16(adst + (m * A_STRIDE + k4 * 4) * 4,                         \
                       &g_Weff[(mBase + m) * CH + (k0) + k4 * 4]);                 \
        }                                                                          \
        _Pragma("unroll")                                                          \
        for (int it = 0; it < 4; it++) {                                           \
            int idx = tid + it * 256;                                              \
            int k = idx >> 5, n4 = idx & 31;                                       \
            cp_async16(bdst + (k * B_STRIDE + n4 * 4) * 4,                         \
                       &xb[(size_t)((k0) + k) * NB + n0 + n4 * 4]);                \
        }                                                                          \
    }

    LOAD_CHUNK(0, 0);
    cp_commit();

    for (int i = 0; i < 8; i++) {
        int buf = i & 1;
        if (i < 7) {
            LOAD_CHUNK((i + 1) & 1, (i + 1) * KC);
            cp_commit();
            asm volatile("cp.async.wait_group 1;");
        } else {
            asm volatile("cp.async.wait_group 0;");
        }
        __syncthreads();

        const float* Ab = smf + OFF_A + buf * A_BUF_FL;
        const float* Bb = smf + OFF_B + buf * B_BUF_FL;

        #pragma unroll
        for (int kc = 0; kc < 4; kc++) {
            int k8 = kc * 8;
            uint32_t afr[2][4];
            #pragma unroll
            for (int mt = 0; mt < 2; mt++) {
                int m = wRow * 32 + mt * 16 + r;
                afr[mt][0] = f2tf32(Ab[m * A_STRIDE + k8 + t]);
                afr[mt][1] = f2tf32(Ab[(m + 8) * A_STRIDE + k8 + t]);
                afr[mt][2] = f2tf32(Ab[m * A_STRIDE + k8 + t + 4]);
                afr[mt][3] = f2tf32(Ab[(m + 8) * A_STRIDE + k8 + t + 4]);
            }
            uint32_t bfr[8][2];
            #pragma unroll
            for (int nt = 0; nt < 8; nt++) {
                int n = wCol * 64 + nt * 8 + r;
                bfr[nt][0] = f2tf32(Bb[(k8 + t) * B_STRIDE + n]);
                bfr[nt][1] = f2tf32(Bb[(k8 + t + 4) * B_STRIDE + n]);
            }
            #pragma unroll
            for (int mt = 0; mt < 2; mt++)
                #pragma unroll
                for (int nt = 0; nt < 8; nt++)
                    mma_tf32(acc[mt][nt], afr[mt], bfr[nt]);
        }
        __syncthreads();
    }

    // ---------------- epilogue 1: stats only (y not written) ----------------
    float* s_red = smf + OFF_RED;
    #pragma unroll
    for (int mt = 0; mt < 2; mt++) {
        #pragma unroll
        for (int rv = 0; rv < 2; rv++) {
            int rl = wRow * 32 + mt * 16 + rv * 8 + r;
            int rg = mBase + rl;
            float bo = bout[rg];
            float ps = 0.f, pq = 0.f;
            #pragma unroll
            for (int nt = 0; nt < 8; nt++) {
                int col = n0 + wCol * 64 + nt * 8 + t * 2;
                size_t gi = (size_t)rg * NB + col;
                float2 xv = *(const float2*)&xb[gi];
                float y0 = xv.x + fmaxf(acc[mt][nt][rv * 2 + 0] + bo, 0.f);
                float y1 = xv.y + fmaxf(acc[mt][nt][rv * 2 + 1] + bo, 0.f);
                ps += y0 + y1;
                pq += y0 * y0 + y1 * y1;
            }
            atomicAdd(&s_red[rl], ps);
            atomicAdd(&s_red[128 + rl], pq);
        }
    }
    __syncthreads();
    if (tid < 128) {
        atomicAdd(&g_sum[mBase + tid],   s_red[tid]);
        atomicAdd(&g_sumsq[mBase + tid], s_red[128 + tid]);
    }
    __threadfence();
    __syncthreads();

    // ---------------- grid-wide barrier (all 256 CTAs co-resident) ----------
    if (tid == 0) {
        atomicAdd(&g_bar, 1u);
        unsigned v;
        do {
            asm volatile("ld.acquire.gpu.u32 %0, [%1];" : "=r"(v) : "l"(&g_bar));
        } while (v < GRID_TOTAL);
    }
    __syncthreads();

    // ---------------- epilogue 2: normalize + single store ------------------
    #pragma unroll
    for (int mt = 0; mt < 2; mt++) {
        #pragma unroll
        for (int rv = 0; rv < 2; rv++) {
            int rl = wRow * 32 + mt * 16 + rv * 8 + r;
            int rg = mBase + rl;
            float bo = bout[rg];
            float m  = __ldcg(&g_sum[rg])   * (1.0f / BN_COUNT);
            float vv = __ldcg(&g_sumsq[rg]) * (1.0f / BN_COUNT) - m * m;
            float sc = rsqrtf(vv + 1e-5f);        // gamma == applied below
            float bi = -m * sc;
            #pragma unroll
            for (int nt = 0; nt < 8; nt++) {
                int col = n0 + wCol * 64 + nt * 8 + t * 2;
                size_t gi = (size_t)rg * NB + col;
                float2 xv = *(const float2*)&xb[gi];
                float y0 = xv.x + fmaxf(acc[mt][nt][rv * 2 + 0] + bo, 0.f);
                float y1 = xv.y + fmaxf(acc[mt][nt][rv * 2 + 1] + bo, 0.f);
                *(float2*)&ob[gi] = make_float2(y0 * sc + bi, y1 * sc + bi);
            }
        }
    }
}

// ---------------------------------------------------------------------------
// Note: gamma == 1, beta == 0 in this problem's setup, but we must still honor
// them; apply gamma/beta correctly via a tiny pre-fold into scale/bias.
// To stay fully general we fold gamma/beta inside fused_kernel using the
// actual tensors: replace sc/bi computation with gamma/beta-aware version.
// (Implemented below via a second variant used in kernel_launch.)
// ---------------------------------------------------------------------------
__global__ void __launch_bounds__(256, 1)
foldgb_kernel(const float* __restrict__ gamma,
              const float* __restrict__ beta,
              float* __restrict__ dummy) { (void)gamma; (void)beta; (void)dummy; }

extern "C" void kernel_launch(void* const* d_in, const int* in_sizes, int n_in,
                              void* d_out, int out_size);

// gamma/beta-aware fused kernel wrapper: we pass gamma,beta and use them.
__global__ void __launch_bounds__(256, 2)
fused_kernel_gb(const float* __restrict__ x,
                const float* __restrict__ bout,
                const float* __restrict__ gamma,
                const float* __restrict__ beta,
                float* __restrict__ out);

// Re-implement with gamma/beta (the version actually launched).
__global__ void __launch_bounds__(256, 2)
fused_kernel_gb(const float* __restrict__ x,
                const float* __restrict__ bout,
                const float* __restrict__ gamma,
                const float* __restrict__ beta,
                float* __restrict__ out) {
    extern __shared__ float smf[];
    uint32_t smb = smem_u32(smf);

    int tid  = threadIdx.x;
    int wid  = tid >> 5;
    int lane = tid & 31;
    int r    = lane >> 2;
    int t    = lane & 3;
    int wRow = wid & 3;
    int wCol = wid >> 2;

    int n0    = blockIdx.x * NT;
    int mBase = blockIdx.y * MT;
    int b     = blockIdx.z;
    const float* xb = x   + (size_t)b * CH * NB;
    float*       ob = out + (size_t)b * CH * NB;

    smf[OFF_RED + tid] = 0.f;

    float acc[2][8][4];
    #pragma unroll
    for (int mt = 0; mt < 2; mt++)
        #pragma unroll
        for (int nt = 0; nt < 8; nt++)
            #pragma unroll
            for (int q = 0; q < 4; q++) acc[mt][nt][q] = 0.f;

    LOAD_CHUNK(0, 0);
    cp_commit();

    for (int i = 0; i < 8; i++) {
        int buf = i & 1;
        if (i < 7) {
            LOAD_CHUNK((i + 1) & 1, (i + 1) * KC);
            cp_commit();
            asm volatile("cp.async.wait_group 1;");
        } else {
            asm volatile("cp.async.wait_group 0;");
        }
        __syncthreads();

        const float* Ab = smf + OFF_A + buf * A_BUF_FL;
        const float* Bb = smf + OFF_B + buf * B_BUF_FL;

        #pragma unroll
        for (int kc = 0; kc < 4; kc++) {
            int k8 = kc * 8;
            uint32_t afr[2][4];
            #pragma unroll
            for (int mt = 0; mt < 2; mt++) {
                int m = wRow * 32 + mt * 16 + r;
                afr[mt][0] = f2tf32(Ab[m * A_STRIDE + k8 + t]);
                afr[mt][1] = f2tf32(Ab[(m + 8) * A_STRIDE + k8 + t]);
                afr[mt][2] = f2tf32(Ab[m * A_STRIDE + k8 + t + 4]);
                afr[mt][3] = f2tf32(Ab[(m + 8) * A_STRIDE + k8 + t + 4]);
            }
            uint32_t bfr[8][2];
            #pragma unroll
            for (int nt = 0; nt < 8; nt++) {
                int n = wCol * 64 + nt * 8 + r;
                bfr[nt][0] = f2tf32(Bb[(k8 + t) * B_STRIDE + n]);
                bfr[nt][1] = f2tf32(Bb[(k8 + t + 4) * B_STRIDE + n]);
            }
            #pragma unroll
            for (int mt = 0; mt < 2; mt++)
                #pragma unroll
                for (int nt = 0; nt < 8; nt++)
                    mma_tf32(acc[mt][nt], afr[mt], bfr[nt]);
        }
        __syncthreads();
    }

    float* s_red = smf + OFF_RED;
    #pragma unroll
    for (int mt = 0; mt < 2; mt++) {
        #pragma unroll
        for (int rv = 0; rv < 2; rv++) {
            int rl = wRow * 32 + mt * 16 + rv * 8 + r;
            int rg = mBase + rl;
            float bo = bout[rg];
            float ps = 0.f, pq = 0.f;
            #pragma unroll
            for (int nt = 0; nt < 8; nt++) {
                int col = n0 + wCol * 64 + nt * 8 + t * 2;
                size_t gi = (size_t)rg * NB + col;
                float2 xv = *(const float2*)&xb[gi];
                float y0 = xv.x + fmaxf(acc[mt][nt][rv * 2 + 0] + bo, 0.f);
                float y1 = xv.y + fmaxf(acc[mt][nt][rv * 2 + 1] + bo, 0.f);
                ps += y0 + y1;
                pq += y0 * y0 + y1 * y1;
            }
            atomicAdd(&s_red[rl], ps);
            atomicAdd(&s_red[128 + rl], pq);
        }
    }
    __syncthreads();
    if (tid < 128) {
        atomicAdd(&g_sum[mBase + tid],   s_red[tid]);
        atomicAdd(&g_sumsq[mBase + tid], s_red[128 + tid]);
    }
    __threadfence();
    __syncthreads();

    if (tid == 0) {
        atomicAdd(&g_bar, 1u);
        unsigned v;
        do {
            asm volatile("ld.acquire.gpu.u32 %0, [%1];" : "=r"(v) : "l"(&g_bar));
        } while (v < GRID_TOTAL);
    }
    __syncthreads();

    #pragma unroll
    for (int mt = 0; mt < 2; mt++) {
        #pragma unroll
        for (int rv = 0; rv < 2; rv++) {
            int rl = wRow * 32 + mt * 16 + rv * 8 + r;
            int rg = mBase + rl;
            float bo = bout[rg];
            float m  = __ldcg(&g_sum[rg])   * (1.0f / BN_COUNT);
            float vv = __ldcg(&g_sumsq[rg]) * (1.0f / BN_COUNT) - m * m;
            float sc = gamma[rg] * rsqrtf(vv + 1e-5f);
            float bi = beta[rg] - m * sc;
            #pragma unroll
            for (int nt = 0; nt < 8; nt++) {
                int col = n0 + wCol * 64 + nt * 8 + t * 2;
                size_t gi = (size_t)rg * NB + col;
                float2 xv = *(const float2*)&xb[gi];
                float y0 = xv.x + fmaxf(acc[mt][nt][rv * 2 + 0] + bo, 0.f);
                float y1 = xv.y + fmaxf(acc[mt][nt][rv * 2 + 1] + bo, 0.f);
                *(float2*)&ob[gi] = make_float2(y0 * sc + bi, y1 * sc + bi);
            }
        }
    }
}

// ---------------------------------------------------------------------------
extern "C" void kernel_launch(void* const* d_in, const int* in_sizes, int n_in,
                              void* d_out, int out_size) {
    const float* x     = (const float*)d_in[0];
    // d_in[1]=Wk, d_in[2]=Wq unused (softmax row-sums == 1)
    const float* Wv    = (const float*)d_in[3];
    const float* Wout  = (const float*)d_in[4];
    const float* bout  = (const float*)d_in[5];
    const float* gamma = (const float*)d_in[6];
    const float* beta  = (const float*)d_in[7];
    float* out = (float*)d_out;

    cudaFuncSetAttribute(fused_kernel_gb,
                         cudaFuncAttributeMaxDynamicSharedMemorySize, SMEM_BYTES);

    zero_kernel<<<64, 256>>>();
    weff_kernel<<<dim3(4, 4, 4), 256>>>(Wout, Wv);
    fused_kernel_gb<<<dim3(NB / NT, CH / MT, BATCH), 256, SMEM_BYTES>>>(
        x, bout, gamma, beta, out);
}